// round 8
// baseline (speedup 1.0000x reference)
#include <cuda_runtime.h>
#include <cuda_fp16.h>
#include <cstdint>
#include <mma.h>

using namespace nvcuda;

#define T_      8
#define H_      64
#define W_      64
#define C_      256
#define HEADS_  8
#define WS_     7
#define NPIX    (T_ * H_ * W_)          // 32768
#define M_      NPIX
#define N_      512
#define K_      256
#define NS_     (3 * WS_ * WS_)         // 147
#define SCALE_  0.17677669529663687f    // 32^-0.5

// projected q (pre-scaled) / k, fp16
__device__ __align__(16) __half g_qh[(size_t)NPIX * 256];
__device__ __align__(16) __half g_kh[(size_t)NPIX * 256];

// ---------------------------------------------------------------------------
// GEMM: qk[m,n] = sum_k x[m,k] * W_qk[n,k]
// fp16 WMMA, 128x128 tile, fp32 in (converted at staging), fp16 out
// ---------------------------------------------------------------------------
#define GBM 128
#define GBN 128
#define GLD 40          // halfs pitch

__device__ __forceinline__ void cvt8(const float4 u, const float4 v, uint4& o)
{
    __half2 p0 = __floats2half2_rn(u.x, u.y);
    __half2 p1 = __floats2half2_rn(u.z, u.w);
    __half2 p2 = __floats2half2_rn(v.x, v.y);
    __half2 p3 = __floats2half2_rn(v.z, v.w);
    o.x = *(unsigned*)&p0; o.y = *(unsigned*)&p1;
    o.z = *(unsigned*)&p2; o.w = *(unsigned*)&p3;
}

__global__ void __launch_bounds__(256) gemm_qk_kernel(
    const float* __restrict__ x, const float* __restrict__ wqk)
{
    __shared__ __align__(16) char SB[40960];
    __half* As = (__half*)SB;            // 128 x 40
    __half* Bs = As + 5120;              // 128 x 40

    const int m0   = blockIdx.x * GBM;
    const int n0   = blockIdx.y * GBN;
    const int tid  = threadIdx.x;
    const int wid  = tid >> 5;
    const int lane = tid & 31;
    const int wm   = wid & 3;    // 4 M-groups of 32 rows
    const int wn   = wid >> 2;   // 2 N-groups of 64 cols

    wmma::fragment<wmma::accumulator, 16, 16, 16, float> acc[2][4];
    #pragma unroll
    for (int i = 0; i < 2; i++)
        #pragma unroll
        for (int j = 0; j < 4; j++)
            wmma::fill_fragment(acc[i][j], 0.0f);

    const int lr = tid >> 1;            // 0..127
    const int lc = (tid & 1) * 16;      // 0 or 16 (floats / halfs)

    for (int kt = 0; kt < K_; kt += 32) {
        const float* ap = x   + (size_t)(m0 + lr) * K_ + kt + lc;
        const float* bp = wqk + (size_t)(n0 + lr) * K_ + kt + lc;
        uint4 oa0, oa1, ob0, ob1;
        cvt8(*(const float4*)(ap),     *(const float4*)(ap + 4),  oa0);
        cvt8(*(const float4*)(ap + 8), *(const float4*)(ap + 12), oa1);
        cvt8(*(const float4*)(bp),     *(const float4*)(bp + 4),  ob0);
        cvt8(*(const float4*)(bp + 8), *(const float4*)(bp + 12), ob1);
        __syncthreads();
        *(uint4*)(As + lr * GLD + lc)     = oa0;
        *(uint4*)(As + lr * GLD + lc + 8) = oa1;
        *(uint4*)(Bs + lr * GLD + lc)     = ob0;
        *(uint4*)(Bs + lr * GLD + lc + 8) = ob1;
        __syncthreads();

        #pragma unroll
        for (int kk = 0; kk < 32; kk += 16) {
            wmma::fragment<wmma::matrix_a, 16, 16, 16, __half, wmma::row_major> af0, af1;
            wmma::load_matrix_sync(af0, As + (wm * 32)      * GLD + kk, GLD);
            wmma::load_matrix_sync(af1, As + (wm * 32 + 16) * GLD + kk, GLD);
            #pragma unroll
            for (int j = 0; j < 4; j++) {
                wmma::fragment<wmma::matrix_b, 16, 16, 16, __half, wmma::col_major> bf;
                wmma::load_matrix_sync(bf, Bs + (wn * 64 + j * 16) * GLD + kk, GLD);
                wmma::mma_sync(acc[0][j], af0, bf, acc[0][j]);
                wmma::mma_sync(acc[1][j], af1, bf, acc[1][j]);
            }
        }
    }

    // epilogue: restage 16 rows at a time, convert to fp16 (q pre-scaled)
    __syncthreads();
    float* wbuf = (float*)SB + wid * 1088;   // 16 rows x pitch 68
    const float sc = (n0 < 256) ? SCALE_ : 1.0f;
    const int row  = lane >> 1;
    const int colh = (lane & 1) * 32;

    #pragma unroll
    for (int i = 0; i < 2; i++) {
        #pragma unroll
        for (int j = 0; j < 4; j++)
            wmma::store_matrix_sync(wbuf + j * 16, acc[i][j], 68, wmma::mem_row_major);
        __syncwarp();

        const float* src = wbuf + row * 68 + colh;
        #pragma unroll
        for (int g = 0; g < 2; g++) {
            float4 u0 = *(const float4*)(src + g * 16);
            float4 u1 = *(const float4*)(src + g * 16 + 4);
            float4 u2 = *(const float4*)(src + g * 16 + 8);
            float4 u3 = *(const float4*)(src + g * 16 + 12);
            u0.x *= sc; u0.y *= sc; u0.z *= sc; u0.w *= sc;
            u1.x *= sc; u1.y *= sc; u1.z *= sc; u1.w *= sc;
            u2.x *= sc; u2.y *= sc; u2.z *= sc; u2.w *= sc;
            u3.x *= sc; u3.y *= sc; u3.z *= sc; u3.w *= sc;
            uint4 o0, o1;
            cvt8(u0, u1, o0);
            cvt8(u2, u3, o1);
            const int gr = m0 + wm * 32 + i * 16 + row;
            const int gc = n0 + wn * 64 + colh + g * 16;
            __half* dst = (n0 < 256) ? (g_qh + (size_t)gr * 256 + gc)
                                     : (g_kh + (size_t)gr * 256 + (gc - 256));
            *(uint4*)(dst)     = o0;
            *(uint4*)(dst + 8) = o1;
        }
        __syncwarp();
    }
}

// ---------------------------------------------------------------------------
// Attention: one block per 2x2 pixel tile; warp-per-key over 4 pixels
// (key-major order so L1 captures cross-pixel row reuse)
// ---------------------------------------------------------------------------
__device__ __forceinline__ int reflect_idx(int idx, int L)
{
    const int period = 2 * (L - 1);
    int m = idx % period;
    if (m < 0) m += period;
    return (m > L - 1) ? (period - m) : m;
}

__global__ void __launch_bounds__(256) attn_kernel(
    const float* __restrict__ flows, float* __restrict__ out)
{
    const int bid = blockIdx.x;          // 8192 tiles
    const int t   = bid >> 10;
    const int th  = (bid >> 5) & 31;
    const int tw  = bid & 31;
    const int h0  = th * 2;
    const int w0  = tw * 2;

    __shared__ int   off_s[4][NS_];            // 2352 B
    __shared__ float fl_s[4][NS_ * 3];         // 7056 B
    __shared__ float attn_s[4][HEADS_ * NS_];  // 18816 B
    __shared__ int   s_fl[4][4];

    const int tid  = threadIdx.x;
    const int warp = tid >> 5;
    const int lane = tid & 31;

    if (tid < 16) {
        const int p   = tid >> 2;
        const int idx = tid & 3;
        const int hwp = (h0 + (p >> 1)) * 64 + w0 + (p & 1);
        const int p_  = idx >> 1, c_ = idx & 1;
        s_fl[p][idx] = (int)rintf(flows[(size_t)((t * 2 + p_) * 2 + c_) * 4096 + hwp]);
    }
    __syncthreads();

    for (int e = tid; e < 4 * NS_; e += 256) {
        const int p  = e / NS_;
        const int s  = e - p * NS_;
        const int hp = h0 + (p >> 1);
        const int wp = w0 + (p & 1);
        const int slot = (s >= 49) + (s >= 98);
        const int r = s - slot * 49;
        const int a = r / 7;
        const int b = r - a * 7;
        int di = 0, dj = 0, tp = t;
        if (slot == 1) { tp = (t + 1 < T_) ? t + 1 : t - 2; di = s_fl[p][0]; dj = s_fl[p][1]; }
        if (slot == 2) { tp = (t - 1 >= 0) ? t - 1 : t + 2; di = s_fl[p][2]; dj = s_fl[p][3]; }
        const int li = reflect_idx(hp + di + a - 3, H_);
        const int lj = reflect_idx(wp + dj + b - 3, W_);
        off_s[p][s] = (tp << 12) + li * 64 + lj;
        fl_s[p][s * 3 + 0] = (float)(tp - t);
        fl_s[p][s * 3 + 1] = (float)(li - hp);
        fl_s[p][s * 3 + 2] = (float)(lj - wp);
    }
    __syncthreads();

    // q fragments for the 4 pixels (pre-scaled fp16), lane covers 8 channels
    uint4 qv[4];
    #pragma unroll
    for (int p = 0; p < 4; p++) {
        const int pixp = (t << 12) + (h0 + (p >> 1)) * 64 + w0 + (p & 1);
        qv[p] = *(const uint4*)(g_qh + (size_t)pixp * 256 + lane * 8);
    }

    const __half* kb = g_kh + lane * 8;

    for (int s = warp; s < NS_; s += 8) {
        #pragma unroll
        for (int p = 0; p < 4; p++) {
            const int off = off_s[p][s];
            const uint4 kv = *(const uint4*)(kb + ((size_t)off << 8));
            const __half2 k0 = *(const __half2*)&kv.x;
            const __half2 k1 = *(const __half2*)&kv.y;
            const __half2 k2 = *(const __half2*)&kv.z;
            const __half2 k3 = *(const __half2*)&kv.w;
            __half2 acc = __hmul2(k0, *(const __half2*)&qv[p].x);
            acc = __hfma2(k1, *(const __half2*)&qv[p].y, acc);
            acc = __hfma2(k2, *(const __half2*)&qv[p].z, acc);
            acc = __hfma2(k3, *(const __half2*)&qv[p].w, acc);
            float v = __half2float(__hadd(__low2half(acc), __high2half(acc)));
            v += __shfl_xor_sync(0xffffffffu, v, 1);
            v += __shfl_xor_sync(0xffffffffu, v, 2);
            if ((lane & 3) == 0)
                attn_s[p][(lane >> 2) * NS_ + s] = v;      // head = lane>>2
        }
    }
    __syncthreads();

    // attn stores: (1, HEADS, T, H, W, 147)
    #pragma unroll
    for (int p = 0; p < 4; p++) {
        const int hwp = (h0 + (p >> 1)) * 64 + w0 + (p & 1);
        #pragma unroll
        for (int head = 0; head < HEADS_; head++) {
            if (tid < NS_)
                out[(size_t)((head * T_ + t) * 4096 + hwp) * NS_ + tid] =
                    attn_s[p][head * NS_ + tid];
        }
    }

    // flows_k stores: (1, HEADS, T, H, W, 147, 3)
    const size_t FBASE = (size_t)HEADS_ * T_ * 4096 * NS_;  // 38,535,168
    #pragma unroll
    for (int p = 0; p < 4; p++) {
        const int hwp = (h0 + (p >> 1)) * 64 + w0 + (p & 1);
        #pragma unroll
        for (int head = 0; head < HEADS_; head++) {
            const size_t base = FBASE + (size_t)((head * T_ + t) * 4096 + hwp) * (NS_ * 3);
            out[base + tid] = fl_s[p][tid];
            if (tid + 256 < NS_ * 3)
                out[base + tid + 256] = fl_s[p][tid + 256];
        }
    }
}

// ---------------------------------------------------------------------------
extern "C" void kernel_launch(void* const* d_in, const int* in_sizes, int n_in,
                              void* d_out, int out_size)
{
    const float* x     = (const float*)d_in[0];   // (8,64,64,256)
    const float* flows = (const float*)d_in[1];   // (1,8,2,2,64,64)
    const float* wqk   = (const float*)d_in[2];   // (512,256)
    float* out = (float*)d_out;

    dim3 gg(M_ / GBM, N_ / GBN);
    gemm_qk_kernel<<<gg, 256>>>(x, wqk);
    attn_kernel<<<NPIX / 4, 256>>>(flows, out);
}

// round 9
// speedup vs baseline: 1.1372x; 1.1372x over previous
#include <cuda_runtime.h>
#include <cuda_fp16.h>
#include <cstdint>
#include <mma.h>

using namespace nvcuda;

#define T_      8
#define H_      64
#define W_      64
#define C_      256
#define HEADS_  8
#define WS_     7
#define NPIX    (T_ * H_ * W_)          // 32768
#define M_      NPIX
#define N_      512
#define K_      256
#define NS_     (3 * WS_ * WS_)         // 147
#define SCALE_  0.17677669529663687f    // 32^-0.5

// projected q (pre-scaled) / k, fp16
__device__ __align__(16) __half g_qh[(size_t)NPIX * 256];
__device__ __align__(16) __half g_kh[(size_t)NPIX * 256];

// ---------------------------------------------------------------------------
// GEMM: qk[m,n] = sum_k x[m,k] * W_qk[n,k]
// fp16 WMMA, 128x128 tile, fp32 in (converted at staging), fp16 out
// ---------------------------------------------------------------------------
#define GBM 128
#define GBN 128
#define GLD 40          // halfs pitch

__device__ __forceinline__ void cvt8(const float4 u, const float4 v, uint4& o)
{
    __half2 p0 = __floats2half2_rn(u.x, u.y);
    __half2 p1 = __floats2half2_rn(u.z, u.w);
    __half2 p2 = __floats2half2_rn(v.x, v.y);
    __half2 p3 = __floats2half2_rn(v.z, v.w);
    o.x = *(unsigned*)&p0; o.y = *(unsigned*)&p1;
    o.z = *(unsigned*)&p2; o.w = *(unsigned*)&p3;
}

__global__ void __launch_bounds__(256) gemm_qk_kernel(
    const float* __restrict__ x, const float* __restrict__ wqk)
{
    __shared__ __align__(16) char SB[40960];
    __half* As = (__half*)SB;            // 128 x 40
    __half* Bs = As + 5120;              // 128 x 40

    const int m0   = blockIdx.x * GBM;
    const int n0   = blockIdx.y * GBN;
    const int tid  = threadIdx.x;
    const int wid  = tid >> 5;
    const int lane = tid & 31;
    const int wm   = wid & 3;
    const int wn   = wid >> 2;

    wmma::fragment<wmma::accumulator, 16, 16, 16, float> acc[2][4];
    #pragma unroll
    for (int i = 0; i < 2; i++)
        #pragma unroll
        for (int j = 0; j < 4; j++)
            wmma::fill_fragment(acc[i][j], 0.0f);

    const int lr = tid >> 1;
    const int lc = (tid & 1) * 16;

    for (int kt = 0; kt < K_; kt += 32) {
        const float* ap = x   + (size_t)(m0 + lr) * K_ + kt + lc;
        const float* bp = wqk + (size_t)(n0 + lr) * K_ + kt + lc;
        uint4 oa0, oa1, ob0, ob1;
        cvt8(*(const float4*)(ap),     *(const float4*)(ap + 4),  oa0);
        cvt8(*(const float4*)(ap + 8), *(const float4*)(ap + 12), oa1);
        cvt8(*(const float4*)(bp),     *(const float4*)(bp + 4),  ob0);
        cvt8(*(const float4*)(bp + 8), *(const float4*)(bp + 12), ob1);
        __syncthreads();
        *(uint4*)(As + lr * GLD + lc)     = oa0;
        *(uint4*)(As + lr * GLD + lc + 8) = oa1;
        *(uint4*)(Bs + lr * GLD + lc)     = ob0;
        *(uint4*)(Bs + lr * GLD + lc + 8) = ob1;
        __syncthreads();

        #pragma unroll
        for (int kk = 0; kk < 32; kk += 16) {
            wmma::fragment<wmma::matrix_a, 16, 16, 16, __half, wmma::row_major> af0, af1;
            wmma::load_matrix_sync(af0, As + (wm * 32)      * GLD + kk, GLD);
            wmma::load_matrix_sync(af1, As + (wm * 32 + 16) * GLD + kk, GLD);
            #pragma unroll
            for (int j = 0; j < 4; j++) {
                wmma::fragment<wmma::matrix_b, 16, 16, 16, __half, wmma::col_major> bf;
                wmma::load_matrix_sync(bf, Bs + (wn * 64 + j * 16) * GLD + kk, GLD);
                wmma::mma_sync(acc[0][j], af0, bf, acc[0][j]);
                wmma::mma_sync(acc[1][j], af1, bf, acc[1][j]);
            }
        }
    }

    __syncthreads();
    float* wbuf = (float*)SB + wid * 1088;   // 16 rows x pitch 68
    const float sc = (n0 < 256) ? SCALE_ : 1.0f;
    const int row  = lane >> 1;
    const int colh = (lane & 1) * 32;

    #pragma unroll
    for (int i = 0; i < 2; i++) {
        #pragma unroll
        for (int j = 0; j < 4; j++)
            wmma::store_matrix_sync(wbuf + j * 16, acc[i][j], 68, wmma::mem_row_major);
        __syncwarp();

        const float* src = wbuf + row * 68 + colh;
        #pragma unroll
        for (int g = 0; g < 2; g++) {
            float4 u0 = *(const float4*)(src + g * 16);
            float4 u1 = *(const float4*)(src + g * 16 + 4);
            float4 u2 = *(const float4*)(src + g * 16 + 8);
            float4 u3 = *(const float4*)(src + g * 16 + 12);
            u0.x *= sc; u0.y *= sc; u0.z *= sc; u0.w *= sc;
            u1.x *= sc; u1.y *= sc; u1.z *= sc; u1.w *= sc;
            u2.x *= sc; u2.y *= sc; u2.z *= sc; u2.w *= sc;
            u3.x *= sc; u3.y *= sc; u3.z *= sc; u3.w *= sc;
            uint4 o0, o1;
            cvt8(u0, u1, o0);
            cvt8(u2, u3, o1);
            const int gr = m0 + wm * 32 + i * 16 + row;
            const int gc = n0 + wn * 64 + colh + g * 16;
            __half* dst = (n0 < 256) ? (g_qh + (size_t)gr * 256 + gc)
                                     : (g_kh + (size_t)gr * 256 + (gc - 256));
            *(uint4*)(dst)     = o0;
            *(uint4*)(dst + 8) = o1;
        }
        __syncwarp();
    }
}

// ---------------------------------------------------------------------------
// Attention: one block per 2x2 pixel tile; warp-per-key over 4 pixels.
// Loads batched + software-pipelined for MLP; compute chains independent.
// ---------------------------------------------------------------------------
__device__ __forceinline__ int reflect_idx(int idx, int L)
{
    const int period = 2 * (L - 1);
    int m = idx % period;
    if (m < 0) m += period;
    return (m > L - 1) ? (period - m) : m;
}

__global__ void __launch_bounds__(256) attn_kernel(
    const float* __restrict__ flows, float* __restrict__ out)
{
    const int bid = blockIdx.x;          // 8192 tiles
    const int t   = bid >> 10;
    const int th  = (bid >> 5) & 31;
    const int tw  = bid & 31;
    const int h0  = th * 2;
    const int w0  = tw * 2;

    __shared__ int   off_s[4][NS_ + 8];        // padded for prefetch-overrun
    __shared__ float fl_s[4][NS_ * 3];
    __shared__ float attn_s[4][HEADS_ * NS_];
    __shared__ int   s_fl[4][4];

    const int tid  = threadIdx.x;
    const int warp = tid >> 5;
    const int lane = tid & 31;

    if (tid < 16) {
        const int p   = tid >> 2;
        const int idx = tid & 3;
        const int hwp = (h0 + (p >> 1)) * 64 + w0 + (p & 1);
        const int p_  = idx >> 1, c_ = idx & 1;
        s_fl[p][idx] = (int)rintf(flows[(size_t)((t * 2 + p_) * 2 + c_) * 4096 + hwp]);
    }
    // zero the pad so prefetch beyond NS_ reads a safe index
    if (tid >= 224 && tid < 256) {
        const int p = (tid - 224) >> 3;
        off_s[p][NS_ + ((tid - 224) & 7)] = 0;
    }
    __syncthreads();

    for (int e = tid; e < 4 * NS_; e += 256) {
        const int p  = e / NS_;
        const int s  = e - p * NS_;
        const int hp = h0 + (p >> 1);
        const int wp = w0 + (p & 1);
        const int slot = (s >= 49) + (s >= 98);
        const int r = s - slot * 49;
        const int a = r / 7;
        const int b = r - a * 7;
        int di = 0, dj = 0, tp = t;
        if (slot == 1) { tp = (t + 1 < T_) ? t + 1 : t - 2; di = s_fl[p][0]; dj = s_fl[p][1]; }
        if (slot == 2) { tp = (t - 1 >= 0) ? t - 1 : t + 2; di = s_fl[p][2]; dj = s_fl[p][3]; }
        const int li = reflect_idx(hp + di + a - 3, H_);
        const int lj = reflect_idx(wp + dj + b - 3, W_);
        off_s[p][s] = (tp << 12) + li * 64 + lj;
        fl_s[p][s * 3 + 0] = (float)(tp - t);
        fl_s[p][s * 3 + 1] = (float)(li - hp);
        fl_s[p][s * 3 + 2] = (float)(lj - wp);
    }
    __syncthreads();

    // q fragments for the 4 pixels (pre-scaled fp16); lane covers 8 channels
    __half2 q[4][4];
    #pragma unroll
    for (int p = 0; p < 4; p++) {
        const int pixp = (t << 12) + (h0 + (p >> 1)) * 64 + w0 + (p & 1);
        const uint4 v = *(const uint4*)(g_qh + (size_t)pixp * 256 + lane * 8);
        q[p][0] = *(const __half2*)&v.x;
        q[p][1] = *(const __half2*)&v.y;
        q[p][2] = *(const __half2*)&v.z;
        q[p][3] = *(const __half2*)&v.w;
    }

    const __half* kb = g_kh + lane * 8;
    const int head = lane >> 2;            // 0..7
    const bool wr = (lane & 3) == 0;

    // software-pipelined key loop: batch-load 4 rows, prefetch next 4
    uint4 kv[4];
    #pragma unroll
    for (int p = 0; p < 4; p++)
        kv[p] = *(const uint4*)(kb + ((size_t)off_s[p][warp] << 8));

    for (int s = warp; s < NS_; s += 8) {
        uint4 nv[4];
        #pragma unroll
        for (int p = 0; p < 4; p++)
            nv[p] = *(const uint4*)(kb + ((size_t)off_s[p][s + 8 < NS_ ? s + 8 : NS_] << 8));

        float v0, v1, v2, v3;
        {
            __half2 a0 = __hmul2(*(const __half2*)&kv[0].x, q[0][0]);
            __half2 a1 = __hmul2(*(const __half2*)&kv[1].x, q[1][0]);
            __half2 a2 = __hmul2(*(const __half2*)&kv[2].x, q[2][0]);
            __half2 a3 = __hmul2(*(const __half2*)&kv[3].x, q[3][0]);
            a0 = __hfma2(*(const __half2*)&kv[0].y, q[0][1], a0);
            a1 = __hfma2(*(const __half2*)&kv[1].y, q[1][1], a1);
            a2 = __hfma2(*(const __half2*)&kv[2].y, q[2][1], a2);
            a3 = __hfma2(*(const __half2*)&kv[3].y, q[3][1], a3);
            a0 = __hfma2(*(const __half2*)&kv[0].z, q[0][2], a0);
            a1 = __hfma2(*(const __half2*)&kv[1].z, q[1][2], a1);
            a2 = __hfma2(*(const __half2*)&kv[2].z, q[2][2], a2);
            a3 = __hfma2(*(const __half2*)&kv[3].z, q[3][2], a3);
            a0 = __hfma2(*(const __half2*)&kv[0].w, q[0][3], a0);
            a1 = __hfma2(*(const __half2*)&kv[1].w, q[1][3], a1);
            a2 = __hfma2(*(const __half2*)&kv[2].w, q[2][3], a2);
            a3 = __hfma2(*(const __half2*)&kv[3].w, q[3][3], a3);
            v0 = __half2float(__hadd(__low2half(a0), __high2half(a0)));
            v1 = __half2float(__hadd(__low2half(a1), __high2half(a1)));
            v2 = __half2float(__hadd(__low2half(a2), __high2half(a2)));
            v3 = __half2float(__hadd(__low2half(a3), __high2half(a3)));
        }
        // 4 independent shuffle-reduce chains (latencies overlap)
        v0 += __shfl_xor_sync(0xffffffffu, v0, 1);
        v1 += __shfl_xor_sync(0xffffffffu, v1, 1);
        v2 += __shfl_xor_sync(0xffffffffu, v2, 1);
        v3 += __shfl_xor_sync(0xffffffffu, v3, 1);
        v0 += __shfl_xor_sync(0xffffffffu, v0, 2);
        v1 += __shfl_xor_sync(0xffffffffu, v1, 2);
        v2 += __shfl_xor_sync(0xffffffffu, v2, 2);
        v3 += __shfl_xor_sync(0xffffffffu, v3, 2);
        if (wr) {
            attn_s[0][head * NS_ + s] = v0;
            attn_s[1][head * NS_ + s] = v1;
            attn_s[2][head * NS_ + s] = v2;
            attn_s[3][head * NS_ + s] = v3;
        }
        #pragma unroll
        for (int p = 0; p < 4; p++) kv[p] = nv[p];
    }
    __syncthreads();

    // attn stores: (1, HEADS, T, H, W, 147)
    #pragma unroll
    for (int p = 0; p < 4; p++) {
        const int hwp = (h0 + (p >> 1)) * 64 + w0 + (p & 1);
        #pragma unroll
        for (int head2 = 0; head2 < HEADS_; head2++) {
            if (tid < NS_)
                out[(size_t)((head2 * T_ + t) * 4096 + hwp) * NS_ + tid] =
                    attn_s[p][head2 * NS_ + tid];
        }
    }

    // flows_k stores: (1, HEADS, T, H, W, 147, 3)
    const size_t FBASE = (size_t)HEADS_ * T_ * 4096 * NS_;  // 38,535,168
    #pragma unroll
    for (int p = 0; p < 4; p++) {
        const int hwp = (h0 + (p >> 1)) * 64 + w0 + (p & 1);
        #pragma unroll
        for (int head2 = 0; head2 < HEADS_; head2++) {
            const size_t base = FBASE + (size_t)((head2 * T_ + t) * 4096 + hwp) * (NS_ * 3);
            out[base + tid] = fl_s[p][tid];
            if (tid + 256 < NS_ * 3)
                out[base + tid + 256] = fl_s[p][tid + 256];
        }
    }
}

// ---------------------------------------------------------------------------
extern "C" void kernel_launch(void* const* d_in, const int* in_sizes, int n_in,
                              void* d_out, int out_size)
{
    const float* x     = (const float*)d_in[0];   // (8,64,64,256)
    const float* flows = (const float*)d_in[1];   // (1,8,2,2,64,64)
    const float* wqk   = (const float*)d_in[2];   // (512,256)
    float* out = (float*)d_out;

    dim3 gg(M_ / GBM, N_ / GBN);
    gemm_qk_kernel<<<gg, 256>>>(x, wqk);
    attn_kernel<<<NPIX / 4, 256>>>(flows, out);
}

// round 10
// speedup vs baseline: 1.1830x; 1.0402x over previous
#include <cuda_runtime.h>
#include <cuda_fp16.h>
#include <cstdint>
#include <mma.h>

using namespace nvcuda;

#define T_      8
#define H_      64
#define W_      64
#define C_      256
#define HEADS_  8
#define WS_     7
#define NPIX    (T_ * H_ * W_)          // 32768
#define M_      NPIX
#define N_      512
#define K_      256
#define NS_     (3 * WS_ * WS_)         // 147
#define SCALE_  0.17677669529663687f    // 32^-0.5

// projected q (pre-scaled) / k, fp16
__device__ __align__(16) __half g_qh[(size_t)NPIX * 256];
__device__ __align__(16) __half g_kh[(size_t)NPIX * 256];

__device__ __forceinline__ void cvt8(const float4 u, const float4 v, uint4& o)
{
    __half2 p0 = __floats2half2_rn(u.x, u.y);
    __half2 p1 = __floats2half2_rn(u.z, u.w);
    __half2 p2 = __floats2half2_rn(v.x, v.y);
    __half2 p3 = __floats2half2_rn(v.z, v.w);
    o.x = *(unsigned*)&p0; o.y = *(unsigned*)&p1;
    o.z = *(unsigned*)&p2; o.w = *(unsigned*)&p3;
}

// ---------------------------------------------------------------------------
// GEMM: qk[m,n] = sum_k x[m,k]*W_qk[n,k], A-resident: block owns 128 M-rows,
// loops over all 4 N-chunks with A (fp16) kept in smem. x read exactly once.
// ---------------------------------------------------------------------------
#define ALD 264                 // A pitch in halfs
#define BLD 40                  // B pitch in halfs
#define GSM_AS    0             // A: 128*264*2      = 67584 B
#define GSM_BS    67584         // B: 128*40*2       = 10240 B
#define GSM_WBUF  77824         // wbuf: 8*1088*4    = 34816 B
#define GSM_TOTAL 112640

__global__ void __launch_bounds__(256) gemm_qk_kernel(
    const float* __restrict__ x, const float* __restrict__ wqk)
{
    extern __shared__ __align__(16) char sm[];
    __half* As = (__half*)(sm + GSM_AS);
    __half* Bs = (__half*)(sm + GSM_BS);

    const int m0   = blockIdx.x * 128;
    const int tid  = threadIdx.x;
    const int wid  = tid >> 5;
    const int lane = tid & 31;
    const int wm   = wid & 3;    // 4 M-groups of 32 rows
    const int wn   = wid >> 2;   // 2 N-groups of 64 cols

    const int lr = tid >> 1;            // 0..127
    const int lc16 = (tid & 1) * 16;    // 0 or 16

    // ---- phase 1: stage full A tile (128 x 256) as fp16 ----
    #pragma unroll
    for (int c = 0; c < 8; c++) {
        const int col = c * 32 + lc16;
        const float* ap = x + (size_t)(m0 + lr) * K_ + col;
        uint4 o0, o1;
        cvt8(*(const float4*)(ap),     *(const float4*)(ap + 4),  o0);
        cvt8(*(const float4*)(ap + 8), *(const float4*)(ap + 12), o1);
        *(uint4*)(As + lr * ALD + col)     = o0;
        *(uint4*)(As + lr * ALD + col + 8) = o1;
    }
    __syncthreads();

    // ---- phase 2: loop over 4 N-chunks of 128 ----
    for (int nc = 0; nc < 4; nc++) {
        const int n0 = nc * 128;

        wmma::fragment<wmma::accumulator, 16, 16, 16, float> acc[2][4];
        #pragma unroll
        for (int i = 0; i < 2; i++)
            #pragma unroll
            for (int j = 0; j < 4; j++)
                wmma::fill_fragment(acc[i][j], 0.0f);

        for (int kt = 0; kt < K_; kt += 32) {
            const float* bp = wqk + (size_t)(n0 + lr) * K_ + kt + lc16;
            uint4 ob0, ob1;
            cvt8(*(const float4*)(bp),     *(const float4*)(bp + 4),  ob0);
            cvt8(*(const float4*)(bp + 8), *(const float4*)(bp + 12), ob1);
            __syncthreads();
            *(uint4*)(Bs + lr * BLD + lc16)     = ob0;
            *(uint4*)(Bs + lr * BLD + lc16 + 8) = ob1;
            __syncthreads();

            #pragma unroll
            for (int kk = 0; kk < 32; kk += 16) {
                wmma::fragment<wmma::matrix_a, 16, 16, 16, __half, wmma::row_major> af0, af1;
                wmma::load_matrix_sync(af0, As + (wm * 32)      * ALD + kt + kk, ALD);
                wmma::load_matrix_sync(af1, As + (wm * 32 + 16) * ALD + kt + kk, ALD);
                #pragma unroll
                for (int j = 0; j < 4; j++) {
                    wmma::fragment<wmma::matrix_b, 16, 16, 16, __half, wmma::col_major> bf;
                    wmma::load_matrix_sync(bf, Bs + (wn * 64 + j * 16) * BLD + kk, BLD);
                    wmma::mma_sync(acc[0][j], af0, bf, acc[0][j]);
                    wmma::mma_sync(acc[1][j], af1, bf, acc[1][j]);
                }
            }
        }

        // epilogue for this N-chunk
        float* wbuf = (float*)(sm + GSM_WBUF) + wid * 1088;   // 16 rows x pitch 68
        const float sc = (n0 < 256) ? SCALE_ : 1.0f;
        const int row  = lane >> 1;
        const int colh = (lane & 1) * 32;

        #pragma unroll
        for (int i = 0; i < 2; i++) {
            #pragma unroll
            for (int j = 0; j < 4; j++)
                wmma::store_matrix_sync(wbuf + j * 16, acc[i][j], 68, wmma::mem_row_major);
            __syncwarp();

            const float* src = wbuf + row * 68 + colh;
            #pragma unroll
            for (int g = 0; g < 2; g++) {
                float4 u0 = *(const float4*)(src + g * 16);
                float4 u1 = *(const float4*)(src + g * 16 + 4);
                float4 u2 = *(const float4*)(src + g * 16 + 8);
                float4 u3 = *(const float4*)(src + g * 16 + 12);
                u0.x *= sc; u0.y *= sc; u0.z *= sc; u0.w *= sc;
                u1.x *= sc; u1.y *= sc; u1.z *= sc; u1.w *= sc;
                u2.x *= sc; u2.y *= sc; u2.z *= sc; u2.w *= sc;
                u3.x *= sc; u3.y *= sc; u3.z *= sc; u3.w *= sc;
                uint4 o0, o1;
                cvt8(u0, u1, o0);
                cvt8(u2, u3, o1);
                const int gr = m0 + wm * 32 + i * 16 + row;
                const int gc = n0 + wn * 64 + colh + g * 16;
                __half* dst = (n0 < 256) ? (g_qh + (size_t)gr * 256 + gc)
                                         : (g_kh + (size_t)gr * 256 + (gc - 256));
                *(uint4*)(dst)     = o0;
                *(uint4*)(dst + 8) = o1;
            }
            __syncwarp();
        }
    }
}

// ---------------------------------------------------------------------------
// Attention: one block per 2x2 pixel tile; each warp owns 2 pixels,
// keys strided by 4; batched loads + prefetch for MLP.
// ---------------------------------------------------------------------------
__device__ __forceinline__ int reflect_idx(int idx, int L)
{
    const int period = 2 * (L - 1);
    int m = idx % period;
    if (m < 0) m += period;
    return (m > L - 1) ? (period - m) : m;
}

__global__ void __launch_bounds__(256) attn_kernel(
    const float* __restrict__ flows, float* __restrict__ out)
{
    const int bid = blockIdx.x;          // 8192 tiles
    const int t   = bid >> 10;
    const int th  = (bid >> 5) & 31;
    const int tw  = bid & 31;
    const int h0  = th * 2;
    const int w0  = tw * 2;

    __shared__ int   off_s[4][NS_ + 8];        // padded for prefetch-overrun
    __shared__ float fl_s[4][NS_ * 3];
    __shared__ float attn_s[4][HEADS_ * NS_];
    __shared__ int   s_fl[4][4];

    const int tid  = threadIdx.x;
    const int warp = tid >> 5;
    const int lane = tid & 31;

    if (tid < 16) {
        const int p   = tid >> 2;
        const int idx = tid & 3;
        const int hwp = (h0 + (p >> 1)) * 64 + w0 + (p & 1);
        const int p_  = idx >> 1, c_ = idx & 1;
        s_fl[p][idx] = (int)rintf(flows[(size_t)((t * 2 + p_) * 2 + c_) * 4096 + hwp]);
    }
    if (tid >= 224 && tid < 256) {             // zero the prefetch pad
        const int p = (tid - 224) >> 3;
        off_s[p][NS_ + ((tid - 224) & 7)] = 0;
    }
    __syncthreads();

    for (int e = tid; e < 4 * NS_; e += 256) {
        const int p  = e / NS_;
        const int s  = e - p * NS_;
        const int hp = h0 + (p >> 1);
        const int wp = w0 + (p & 1);
        const int slot = (s >= 49) + (s >= 98);
        const int r = s - slot * 49;
        const int a = r / 7;
        const int b = r - a * 7;
        int di = 0, dj = 0, tp = t;
        if (slot == 1) { tp = (t + 1 < T_) ? t + 1 : t - 2; di = s_fl[p][0]; dj = s_fl[p][1]; }
        if (slot == 2) { tp = (t - 1 >= 0) ? t - 1 : t + 2; di = s_fl[p][2]; dj = s_fl[p][3]; }
        const int li = reflect_idx(hp + di + a - 3, H_);
        const int lj = reflect_idx(wp + dj + b - 3, W_);
        off_s[p][s] = (tp << 12) + li * 64 + lj;
        fl_s[p][s * 3 + 0] = (float)(tp - t);
        fl_s[p][s * 3 + 1] = (float)(li - hp);
        fl_s[p][s * 3 + 2] = (float)(lj - wp);
    }
    __syncthreads();

    // warps 0-3 -> pixels {0,1}, warps 4-7 -> pixels {2,3}; key stride 4
    const int p0    = (warp >> 2) * 2;
    const int sbase = warp & 3;

    __half2 q[2][4];
    #pragma unroll
    for (int i = 0; i < 2; i++) {
        const int p = p0 + i;
        const int pixp = (t << 12) + (h0 + (p >> 1)) * 64 + w0 + (p & 1);
        const uint4 v = *(const uint4*)(g_qh + (size_t)pixp * 256 + lane * 8);
        q[i][0] = *(const __half2*)&v.x;
        q[i][1] = *(const __half2*)&v.y;
        q[i][2] = *(const __half2*)&v.z;
        q[i][3] = *(const __half2*)&v.w;
    }

    const __half* kb = g_kh + lane * 8;
    const int head = lane >> 2;
    const bool wr = (lane & 3) == 0;

    uint4 kv[2];
    kv[0] = *(const uint4*)(kb + ((size_t)off_s[p0][sbase]     << 8));
    kv[1] = *(const uint4*)(kb + ((size_t)off_s[p0 + 1][sbase] << 8));

    for (int s = sbase; s < NS_; s += 4) {
        const int sn = (s + 4 < NS_) ? s + 4 : NS_;
        uint4 nv0 = *(const uint4*)(kb + ((size_t)off_s[p0][sn]     << 8));
        uint4 nv1 = *(const uint4*)(kb + ((size_t)off_s[p0 + 1][sn] << 8));

        __half2 a0 = __hmul2(*(const __half2*)&kv[0].x, q[0][0]);
        __half2 a1 = __hmul2(*(const __half2*)&kv[1].x, q[1][0]);
        a0 = __hfma2(*(const __half2*)&kv[0].y, q[0][1], a0);
        a1 = __hfma2(*(const __half2*)&kv[1].y, q[1][1], a1);
        a0 = __hfma2(*(const __half2*)&kv[0].z, q[0][2], a0);
        a1 = __hfma2(*(const __half2*)&kv[1].z, q[1][2], a1);
        a0 = __hfma2(*(const __half2*)&kv[0].w, q[0][3], a0);
        a1 = __hfma2(*(const __half2*)&kv[1].w, q[1][3], a1);
        float v0 = __half2float(__hadd(__low2half(a0), __high2half(a0)));
        float v1 = __half2float(__hadd(__low2half(a1), __high2half(a1)));
        v0 += __shfl_xor_sync(0xffffffffu, v0, 1);
        v1 += __shfl_xor_sync(0xffffffffu, v1, 1);
        v0 += __shfl_xor_sync(0xffffffffu, v0, 2);
        v1 += __shfl_xor_sync(0xffffffffu, v1, 2);
        if (wr) {
            attn_s[p0][head * NS_ + s]     = v0;
            attn_s[p0 + 1][head * NS_ + s] = v1;
        }
        kv[0] = nv0;
        kv[1] = nv1;
    }
    __syncthreads();

    // attn stores: (1, HEADS, T, H, W, 147)
    #pragma unroll
    for (int p = 0; p < 4; p++) {
        const int hwp = (h0 + (p >> 1)) * 64 + w0 + (p & 1);
        #pragma unroll
        for (int hd = 0; hd < HEADS_; hd++) {
            if (tid < NS_)
                out[(size_t)((hd * T_ + t) * 4096 + hwp) * NS_ + tid] =
                    attn_s[p][hd * NS_ + tid];
        }
    }

    // flows_k stores: (1, HEADS, T, H, W, 147, 3)
    const size_t FBASE = (size_t)HEADS_ * T_ * 4096 * NS_;  // 38,535,168
    #pragma unroll
    for (int p = 0; p < 4; p++) {
        const int hwp = (h0 + (p >> 1)) * 64 + w0 + (p & 1);
        #pragma unroll
        for (int hd = 0; hd < HEADS_; hd++) {
            const size_t base = FBASE + (size_t)((hd * T_ + t) * 4096 + hwp) * (NS_ * 3);
            out[base + tid] = fl_s[p][tid];
            if (tid + 256 < NS_ * 3)
                out[base + tid + 256] = fl_s[p][tid + 256];
        }
    }
}

// ---------------------------------------------------------------------------
extern "C" void kernel_launch(void* const* d_in, const int* in_sizes, int n_in,
                              void* d_out, int out_size)
{
    const float* x     = (const float*)d_in[0];   // (8,64,64,256)
    const float* flows = (const float*)d_in[1];   // (1,8,2,2,64,64)
    const float* wqk   = (const float*)d_in[2];   // (512,256)
    float* out = (float*)d_out;

    cudaFuncSetAttribute(gemm_qk_kernel,
                         cudaFuncAttributeMaxDynamicSharedMemorySize, GSM_TOTAL);

    gemm_qk_kernel<<<M_ / 128, 256, GSM_TOTAL>>>(x, wqk);
    attn_kernel<<<NPIX / 4, 256>>>(flows, out);
}